// round 16
// baseline (speedup 1.0000x reference)
#include <cuda_runtime.h>
#include <math.h>

#define BATCH 4
#define MROWS 2048
#define NPTS  8192
#define NROWS (BATCH*MROWS)   // 8192
#define KNN   20
#define C0    32
#define C1    64
#define C2    256
#define NB0   32              // replicas for bins0 (1024 producer blocks)
#define NB    8               // replicas for bins1/2 (256 producer blocks)
#define EPSB  1e-5f

// ---------------- scratch (device globals; no allocation) ----------------
// single blob so one cudaMemsetAsync clears all stat bins
#define BINS0_OFF 0                       // NB0*2*C0 = 2048
#define BINS1_OFF (NB0*2*C0)              // NB*2*C1  = 1024
#define BINS2_OFF (NB0*2*C0 + NB*2*C1)    // NB*2*C2  = 4096
#define BINS_TOTAL (NB0*2*C0 + NB*2*C1 + NB*2*C2)
__device__ float g_bins[BINS_TOTAL];
#define BINS0(rep,i) g_bins[BINS0_OFF + (rep)*2*C0 + (i)]
#define BINS1(rep,i) g_bins[BINS1_OFF + (rep)*2*C1 + (i)]
#define BINS2(rep,i) g_bins[BINS2_OFF + (rep)*2*C2 + (i)]

__device__ float g_hmm[NROWS][2][C0];   // per (row,channel) pre-BN0 min/max
__device__ float g_h1[NROWS*C1];
__device__ float g_w2T[C1][C2];         // transposed w2: [k][o]
__device__ float g_z[NROWS*C2];

__device__ __forceinline__ float gelu_exact(float x) {
    return 0.5f * x * (1.0f + erff(x * 0.70710678118654752f));
}

// ---------------- K1: warp-per-row neighbor search + BN0 stats + h min/max ----------------
#define K1_WARPS 8
__global__ __launch_bounds__(256)
void k1_scan(const float* __restrict__ centroid, const float* __restrict__ xyz,
             const float* __restrict__ radius,   const float* __restrict__ dist,
             const float* __restrict__ w_xyz,    const float* __restrict__ b_xyz,
             const float* __restrict__ w2)
{
    int t = threadIdx.x, lane = t & 31, w = t >> 5;
    int row = blockIdx.x * K1_WARPS + w;
    unsigned lmask = (1u << lane) - 1u;

    // fold w2 transpose into the first 64 blocks (1 entry/thread)
    if (blockIdx.x < 64) {
        int i = blockIdx.x * 256 + t;
        int k = i >> 8, o = i & 255;
        g_w2T[k][o] = w2[o*C1 + k];
    }

    __shared__ int s_idx[K1_WARPS][KNN];

    const float* __restrict__ drow = dist + (size_t)row * NPTS;
    float r = radius[row];           // issued concurrently with first chunks
    int cnt = 0;

    if (r >= 0.04f) {
        // fast path: 64-elem chunks, 4-deep prefetch (256 elems in flight)
        float da[4], db[4];
#pragma unroll
        for (int q = 0; q < 4; q++) {
            da[q] = drow[q*64 + lane];
            db[q] = drow[q*64 + 32 + lane];
        }
        int base = 0;
#pragma unroll 1
        while (true) {
            unsigned m0 = __ballot_sync(0xffffffffu, da[0] <= r);
            if (da[0] <= r) {
                int pos = cnt + __popc(m0 & lmask);
                if (pos < KNN) s_idx[w][pos] = base + lane;
            }
            cnt += __popc(m0);
            unsigned m1 = __ballot_sync(0xffffffffu, db[0] <= r);
            if (db[0] <= r) {
                int pos = cnt + __popc(m1 & lmask);
                if (pos < KNN) s_idx[w][pos] = base + 32 + lane;
            }
            cnt += __popc(m1);
            if (cnt >= KNN || base + 64 >= NPTS) break;
#pragma unroll
            for (int q = 0; q < 3; q++) { da[q] = da[q+1]; db[q] = db[q+1]; }
            int nf = base + 256;
            if (nf + 64 <= NPTS) { da[3] = drow[nf + lane]; db[3] = drow[nf + 32 + lane]; }
            else                 { da[3] = 2.0f;            db[3] = 2.0f; }
            base += 64;
        }
    } else {
        // slow path (rare): 256-elem chunks, 3-deep prefetch (MLP ~24)
        float buf[4][8];
#pragma unroll
        for (int q = 0; q < 4; q++)
#pragma unroll
            for (int s = 0; s < 8; s++) buf[q][s] = drow[q*256 + s*32 + lane];
        int base = 0;
#pragma unroll 1
        while (true) {
#pragma unroll
            for (int s = 0; s < 8; s++) {
                float d = buf[0][s];
                unsigned m = __ballot_sync(0xffffffffu, d <= r);
                if (d <= r) {
                    int pos = cnt + __popc(m & lmask);
                    if (pos < KNN) s_idx[w][pos] = base + s*32 + lane;
                }
                cnt += __popc(m);
            }
            if (cnt >= KNN || base + 256 >= NPTS) break;
            int nb = base + 1024;
#pragma unroll
            for (int q = 0; q < 3; q++)
#pragma unroll
                for (int s = 0; s < 8; s++) buf[q][s] = buf[q+1][s];
#pragma unroll
            for (int s = 0; s < 8; s++)
                buf[3][s] = (nb < NPTS) ? drow[nb + s*32 + lane] : 2.0f;
            base += 256;
        }
    }
    __syncwarp();

    // pad with first valid index (or N-1 clamp when none)
    if (lane < KNN) {
        int first = (cnt > 0) ? s_idx[w][0] : (NPTS - 1);
        int v = (lane < cnt) ? s_idx[w][lane] : first;
        s_idx[w][lane] = v;
    }
    __syncwarp();

    // BN0 stats + h min/max: lane = channel
    float a0=w_xyz[lane*9+0], a1=w_xyz[lane*9+1], a2=w_xyz[lane*9+2];
    float a3=w_xyz[lane*9+3], a4=w_xyz[lane*9+4], a5=w_xyz[lane*9+5];
    float a6=w_xyz[lane*9+6], a7=w_xyz[lane*9+7], a8=w_xyz[lane*9+8];
    float wc0=a0-a6, wc1=a1-a7, wc2=a2-a8;
    float wp0=a3+a6, wp1=a4+a7, wp2=a5+a8;
    float cx = centroid[row*3+0], cy = centroid[row*3+1], cz = centroid[row*3+2];
    const float* __restrict__ xb = xyz + (size_t)(row >> 11) * NPTS * 3;
    float hbase = b_xyz[lane] + wc0*cx + wc1*cy + wc2*cz;

    float ls = 0.0f, lss = 0.0f, hmin = 1e30f, hmax = -1e30f;
#pragma unroll
    for (int k = 0; k < KNN; k++) {
        int id = s_idx[w][k];           // warp-uniform -> broadcast
        float px = xb[id*3+0], py = xb[id*3+1], pz = xb[id*3+2];
        float h = hbase + wp0*px + wp1*py + wp2*pz;
        ls += h; lss += h*h;
        hmin = fminf(hmin, h); hmax = fmaxf(hmax, h);
    }
    g_hmm[row][0][lane] = hmin;
    g_hmm[row][1][lane] = hmax;
    int rep = row & (NB0 - 1);
    atomicAdd(&BINS0(rep, lane),      ls);
    atomicAdd(&BINS0(rep, C0 + lane), lss);
}

// ---------------- K2: BN0 hull + GELU + w1 -> h1, BN1 stats (no gather) ----------------
#define K2_RPW 4           // rows per warp
__global__ __launch_bounds__(256)
void k2(const float* __restrict__ g0, const float* __restrict__ be0,
        const float* __restrict__ w1)
{
    int t = threadIdx.x, lane = t & 31, w = t >> 5;
    __shared__ float s_sc0[C0], s_bi0[C0];
    __shared__ float s_w1[C1*33];
    __shared__ float s_sum[C1], s_ssq[C1];

    if (t < C0) {
        float s = 0.0f, ss = 0.0f;
        for (int rep = 0; rep < NB0; rep++) { s += BINS0(rep, t); ss += BINS0(rep, C0 + t); }
        float inv = 1.0f / (float)(NROWS * KNN);
        float mean = s * inv;
        float var  = ss * inv - mean * mean;
        float sc   = g0[t] * rsqrtf(var + EPSB);
        s_sc0[t] = sc; s_bi0[t] = be0[t] - mean * sc;
    }
    for (int i = t; i < C1*C0; i += 256) {
        int o = i >> 5, cc = i & 31;
        s_w1[o*33 + cc] = w1[i];
    }
    if (t < C1) { s_sum[t] = 0.0f; s_ssq[t] = 0.0f; }
    __syncthreads();

    float sc = s_sc0[lane], bi = s_bi0[lane];
    float sum0 = 0.0f, ssq0 = 0.0f, sum1 = 0.0f, ssq1 = 0.0f;

#pragma unroll
    for (int rr = 0; rr < K2_RPW; rr++) {
        int row = blockIdx.x * (8*K2_RPW) + w * K2_RPW + rr;
        float hmin = g_hmm[row][0][lane];
        float hmax = g_hmm[row][1][lane];
        float e0 = hmin * sc + bi;
        float e1 = hmax * sc + bi;
        float lo = fminf(e0, e1), hi = fmaxf(e0, e1);
        float m = fmaxf(gelu_exact(lo), gelu_exact(hi));

        float acc0 = 0.0f, acc1 = 0.0f;
#pragma unroll
        for (int cc = 0; cc < C0; cc++) {
            float xv = __shfl_sync(0xffffffffu, m, cc);
            acc0 += s_w1[lane*33 + cc] * xv;
            acc1 += s_w1[(lane+32)*33 + cc] * xv;
        }
        g_h1[(size_t)row*C1 + lane]      = acc0;
        g_h1[(size_t)row*C1 + lane + 32] = acc1;
        sum0 += acc0; ssq0 += acc0*acc0;
        sum1 += acc1; ssq1 += acc1*acc1;
    }

    atomicAdd(&s_sum[lane],      sum0);
    atomicAdd(&s_ssq[lane],      ssq0);
    atomicAdd(&s_sum[lane+32],   sum1);
    atomicAdd(&s_ssq[lane+32],   ssq1);
    __syncthreads();
    if (t < C1) {
        int rep = blockIdx.x & (NB - 1);
        atomicAdd(&BINS1(rep, t),      s_sum[t]);
        atomicAdd(&BINS1(rep, C1 + t), s_ssq[t]);
    }
}

// ---------------- K3: BN1+GELU fused + z = y @ w2^T, 8x4 tile, sw-pipelined ----------------
#define K3_R   32
#define K3_PAD (K3_R + 2)     // 34 floats/row: 8B-aligned row starts, low conflicts
__global__ __launch_bounds__(256)
void k3b(const float* __restrict__ g1, const float* __restrict__ be1)
{
    int t = threadIdx.x, lane = t & 31, w = t >> 5;
    int wc = w >> 2, wr = w & 3;            // warp-col (channels), warp-row (rows)
    int row0 = blockIdx.x * K3_R;
    int o0 = wc * 128 + lane * 4;           // 4 consecutive output channels
    int r0 = wr * 8;                        // 8 rows

    __shared__ float s_sc[C1], s_bi[C1];
    __shared__ float s_yT[C1][K3_PAD];
    __shared__ float s_sum[C2], s_ssq[C2];

    s_sum[t] = 0.0f; s_ssq[t] = 0.0f;
    if (t < C1) {
        float s = 0.0f, ss = 0.0f;
#pragma unroll
        for (int rep = 0; rep < NB; rep++) { s += BINS1(rep, t); ss += BINS1(rep, C1 + t); }
        float inv = 1.0f / (float)NROWS;
        float mean = s * inv;
        float var  = ss * inv - mean * mean;
        float sc   = g1[t] * rsqrtf(var + EPSB);
        s_sc[t] = sc; s_bi[t] = be1[t] - mean * sc;
    }
    __syncthreads();

    // load h1 tile coalesced, BN1+GELU, store transposed [k][r]
#pragma unroll
    for (int i = 0; i < (K3_R*C1)/256; i++) {   // 8
        int j = t + i*256;
        int r = j >> 6, c = j & 63;
        float v = g_h1[(size_t)(row0 + r)*C1 + c];
        s_yT[c][r] = gelu_exact(v * s_sc[c] + s_bi[c]);
    }
    __syncthreads();

    unsigned long long acc[4][4];               // [channel j][row-pair p]
#pragma unroll
    for (int j = 0; j < 4; j++)
#pragma unroll
        for (int p = 0; p < 4; p++) acc[j][p] = 0ull;

    const float4* __restrict__ wt4 = reinterpret_cast<const float4*>(&g_w2T[0][0]);
    const int widx = (o0 >> 2);

    // software pipeline: next-k operands fetched before current-k FFMA2s
    float4 wv = wt4[widx];
    unsigned long long y0, y1, y2, y3;
    {
        const unsigned long long* yp =
            reinterpret_cast<const unsigned long long*>(&s_yT[0][r0]);
        y0 = yp[0]; y1 = yp[1]; y2 = yp[2]; y3 = yp[3];
    }

#pragma unroll 16
    for (int k = 0; k < C1 - 1; k++) {
        // prefetch k+1
        float4 wn = wt4[(k+1)*(C2/4) + widx];
        const unsigned long long* yp =
            reinterpret_cast<const unsigned long long*>(&s_yT[k+1][r0]);
        unsigned long long n0 = yp[0], n1 = yp[1], n2 = yp[2], n3 = yp[3];

        unsigned long long w0, w1, w2, w3;
        asm("mov.b64 %0, {%1, %1};" : "=l"(w0) : "f"(wv.x));
        asm("mov.b64 %0, {%1, %1};" : "=l"(w1) : "f"(wv.y));
        asm("mov.b64 %0, {%1, %1};" : "=l"(w2) : "f"(wv.z));
        asm("mov.b64 %0, {%1, %1};" : "=l"(w3) : "f"(wv.w));
        asm("fma.rn.f32x2 %0, %1, %2, %0;" : "+l"(acc[0][0]) : "l"(y0), "l"(w0));
        asm("fma.rn.f32x2 %0, %1, %2, %0;" : "+l"(acc[0][1]) : "l"(y1), "l"(w0));
        asm("fma.rn.f32x2 %0, %1, %2, %0;" : "+l"(acc[0][2]) : "l"(y2), "l"(w0));
        asm("fma.rn.f32x2 %0, %1, %2, %0;" : "+l"(acc[0][3]) : "l"(y3), "l"(w0));
        asm("fma.rn.f32x2 %0, %1, %2, %0;" : "+l"(acc[1][0]) : "l"(y0), "l"(w1));
        asm("fma.rn.f32x2 %0, %1, %2, %0;" : "+l"(acc[1][1]) : "l"(y1), "l"(w1));
        asm("fma.rn.f32x2 %0, %1, %2, %0;" : "+l"(acc[1][2]) : "l"(y2), "l"(w1));
        asm("fma.rn.f32x2 %0, %1, %2, %0;" : "+l"(acc[1][3]) : "l"(y3), "l"(w1));
        asm("fma.rn.f32x2 %0, %1, %2, %0;" : "+l"(acc[2][0]) : "l"(y0), "l"(w2));
        asm("fma.rn.f32x2 %0, %1, %2, %0;" : "+l"(acc[2][1]) : "l"(y1), "l"(w2));
        asm("fma.rn.f32x2 %0, %1, %2, %0;" : "+l"(acc[2][2]) : "l"(y2), "l"(w2));
        asm("fma.rn.f32x2 %0, %1, %2, %0;" : "+l"(acc[2][3]) : "l"(y3), "l"(w2));
        asm("fma.rn.f32x2 %0, %1, %2, %0;" : "+l"(acc[3][0]) : "l"(y0), "l"(w3));
        asm("fma.rn.f32x2 %0, %1, %2, %0;" : "+l"(acc[3][1]) : "l"(y1), "l"(w3));
        asm("fma.rn.f32x2 %0, %1, %2, %0;" : "+l"(acc[3][2]) : "l"(y2), "l"(w3));
        asm("fma.rn.f32x2 %0, %1, %2, %0;" : "+l"(acc[3][3]) : "l"(y3), "l"(w3));

        wv = wn; y0 = n0; y1 = n1; y2 = n2; y3 = n3;
    }
    {   // peeled last iteration (k = C1-1)
        unsigned long long w0, w1, w2, w3;
        asm("mov.b64 %0, {%1, %1};" : "=l"(w0) : "f"(wv.x));
        asm("mov.b64 %0, {%1, %1};" : "=l"(w1) : "f"(wv.y));
        asm("mov.b64 %0, {%1, %1};" : "=l"(w2) : "f"(wv.z));
        asm("mov.b64 %0, {%1, %1};" : "=l"(w3) : "f"(wv.w));
        asm("fma.rn.f32x2 %0, %1, %2, %0;" : "+l"(acc[0][0]) : "l"(y0), "l"(w0));
        asm("fma.rn.f32x2 %0, %1, %2, %0;" : "+l"(acc[0][1]) : "l"(y1), "l"(w0));
        asm("fma.rn.f32x2 %0, %1, %2, %0;" : "+l"(acc[0][2]) : "l"(y2), "l"(w0));
        asm("fma.rn.f32x2 %0, %1, %2, %0;" : "+l"(acc[0][3]) : "l"(y3), "l"(w0));
        asm("fma.rn.f32x2 %0, %1, %2, %0;" : "+l"(acc[1][0]) : "l"(y0), "l"(w1));
        asm("fma.rn.f32x2 %0, %1, %2, %0;" : "+l"(acc[1][1]) : "l"(y1), "l"(w1));
        asm("fma.rn.f32x2 %0, %1, %2, %0;" : "+l"(acc[1][2]) : "l"(y2), "l"(w1));
        asm("fma.rn.f32x2 %0, %1, %2, %0;" : "+l"(acc[1][3]) : "l"(y3), "l"(w1));
        asm("fma.rn.f32x2 %0, %1, %2, %0;" : "+l"(acc[2][0]) : "l"(y0), "l"(w2));
        asm("fma.rn.f32x2 %0, %1, %2, %0;" : "+l"(acc[2][1]) : "l"(y1), "l"(w2));
        asm("fma.rn.f32x2 %0, %1, %2, %0;" : "+l"(acc[2][2]) : "l"(y2), "l"(w2));
        asm("fma.rn.f32x2 %0, %1, %2, %0;" : "+l"(acc[2][3]) : "l"(y3), "l"(w2));
        asm("fma.rn.f32x2 %0, %1, %2, %0;" : "+l"(acc[3][0]) : "l"(y0), "l"(w3));
        asm("fma.rn.f32x2 %0, %1, %2, %0;" : "+l"(acc[3][1]) : "l"(y1), "l"(w3));
        asm("fma.rn.f32x2 %0, %1, %2, %0;" : "+l"(acc[3][2]) : "l"(y2), "l"(w3));
        asm("fma.rn.f32x2 %0, %1, %2, %0;" : "+l"(acc[3][3]) : "l"(y3), "l"(w3));
    }

    // epilogue: store z (coalesced float4 per row) + per-channel partial stats
    float csum[4] = {0,0,0,0}, cssq[4] = {0,0,0,0};
#pragma unroll
    for (int p = 0; p < 4; p++) {
        float4 lo, hi;
        float zl[4], zh[4];
#pragma unroll
        for (int j = 0; j < 4; j++) {
            zl[j] = __uint_as_float((unsigned)(acc[j][p] & 0xffffffffull));
            zh[j] = __uint_as_float((unsigned)(acc[j][p] >> 32));
            csum[j] += zl[j] + zh[j];
            cssq[j] += zl[j]*zl[j] + zh[j]*zh[j];
        }
        lo.x=zl[0]; lo.y=zl[1]; lo.z=zl[2]; lo.w=zl[3];
        hi.x=zh[0]; hi.y=zh[1]; hi.z=zh[2]; hi.w=zh[3];
        int ra = row0 + r0 + 2*p;
        *reinterpret_cast<float4*>(&g_z[(size_t)ra*C2 + o0])     = lo;
        *reinterpret_cast<float4*>(&g_z[(size_t)(ra+1)*C2 + o0]) = hi;
    }
#pragma unroll
    for (int j = 0; j < 4; j++) {
        atomicAdd(&s_sum[o0 + j], csum[j]);
        atomicAdd(&s_ssq[o0 + j], cssq[j]);
    }
    __syncthreads();
    int rep = blockIdx.x & (NB - 1);
    atomicAdd(&BINS2(rep, t),      s_sum[t]);
    atomicAdd(&BINS2(rep, C2 + t), s_ssq[t]);
}

// ---------------- K4: BN2 normalize -> out ----------------
__global__ __launch_bounds__(256)
void k4(const float* __restrict__ g2, const float* __restrict__ be2,
        float* __restrict__ out)
{
    int t = threadIdx.x;
    __shared__ float s_sc[C2], s_bi[C2];
    {
        float s = 0.0f, ss = 0.0f;
#pragma unroll
        for (int rep = 0; rep < NB; rep++) { s += BINS2(rep, t); ss += BINS2(rep, C2 + t); }
        float inv = 1.0f / (float)NROWS;
        float mean = s * inv;
        float var  = ss * inv - mean * mean;
        float sc   = g2[t] * rsqrtf(var + EPSB);
        s_sc[t] = sc; s_bi[t] = be2[t] - mean * sc;
    }
    __syncthreads();
    const float4* __restrict__ z4 = reinterpret_cast<const float4*>(g_z);
    float4* __restrict__ o4 = reinterpret_cast<float4*>(out);
    const int total4 = NROWS * C2 / 4;
    for (int i = blockIdx.x * 256 + t; i < total4; i += gridDim.x * 256) {
        float4 v = z4[i];
        int c = (i & 63) * 4;
        v.x = v.x * s_sc[c+0] + s_bi[c+0];
        v.y = v.y * s_sc[c+1] + s_bi[c+1];
        v.z = v.z * s_sc[c+2] + s_bi[c+2];
        v.w = v.w * s_sc[c+3] + s_bi[c+3];
        o4[i] = v;
    }
}

// ---------------- launch ----------------
extern "C" void kernel_launch(void* const* d_in, const int* in_sizes, int n_in,
                              void* d_out, int out_size)
{
    const float* centroid = (const float*)d_in[0];
    const float* xyz      = (const float*)d_in[1];
    const float* radius   = (const float*)d_in[2];
    const float* dist     = (const float*)d_in[3];
    const float* w_xyz    = (const float*)d_in[4];
    const float* b_xyz    = (const float*)d_in[5];
    const float* g0       = (const float*)d_in[6];
    const float* be0      = (const float*)d_in[7];
    const float* w1       = (const float*)d_in[8];
    const float* g1       = (const float*)d_in[9];
    const float* be1      = (const float*)d_in[10];
    const float* w2       = (const float*)d_in[11];
    const float* g2       = (const float*)d_in[12];
    const float* be2      = (const float*)d_in[13];
    float* out = (float*)d_out;

    // clear all stat bins with a single captured memset (no alloc)
    void* bins_ptr = nullptr;
    cudaGetSymbolAddress(&bins_ptr, g_bins);
    cudaMemsetAsync(bins_ptr, 0, BINS_TOTAL * sizeof(float));

    k1_scan<<<NROWS / K1_WARPS, 256>>>(centroid, xyz, radius, dist, w_xyz, b_xyz, w2);
    k2<<<NROWS / (8*K2_RPW), 256>>>(g0, be0, w1);
    k3b<<<NROWS / K3_R, 256>>>(g1, be1);
    k4<<<512, 256>>>(g2, be2, out);
}

// round 17
// speedup vs baseline: 1.0654x; 1.0654x over previous
#include <cuda_runtime.h>
#include <math.h>

#define BATCH 4
#define MROWS 2048
#define NPTS  8192
#define NROWS (BATCH*MROWS)   // 8192
#define KNN   20
#define C0    32
#define C1    64
#define C2    256
#define NB0   32              // replicas for bins0 (1024 producer blocks)
#define NB    8               // replicas for bins1/2 (256 producer blocks)
#define EPSB  1e-5f

// ---------------- scratch (device globals; no allocation) ----------------
// single blob so one cudaMemsetAsync clears all stat bins
#define BINS0_OFF 0                       // NB0*2*C0 = 2048
#define BINS1_OFF (NB0*2*C0)              // NB*2*C1  = 1024
#define BINS2_OFF (NB0*2*C0 + NB*2*C1)    // NB*2*C2  = 4096
#define BINS_TOTAL (NB0*2*C0 + NB*2*C1 + NB*2*C2)
__device__ float g_bins[BINS_TOTAL];
#define BINS0(rep,i) g_bins[BINS0_OFF + (rep)*2*C0 + (i)]
#define BINS1(rep,i) g_bins[BINS1_OFF + (rep)*2*C1 + (i)]
#define BINS2(rep,i) g_bins[BINS2_OFF + (rep)*2*C2 + (i)]

__device__ float g_hmm[NROWS][2][C0];   // per (row,channel) pre-BN0 min/max
__device__ float g_h1[NROWS*C1];
__device__ float g_w2T[C1][C2];         // transposed w2: [k][o]
__device__ float g_z[NROWS*C2];

__device__ __forceinline__ float gelu_exact(float x) {
    return 0.5f * x * (1.0f + erff(x * 0.70710678118654752f));
}

// ---------------- K1: warp-per-row neighbor search + BN0 stats + h min/max ----------------
#define K1_WARPS 8
__global__ __launch_bounds__(256)
void k1_scan(const float* __restrict__ centroid, const float* __restrict__ xyz,
             const float* __restrict__ radius,   const float* __restrict__ dist,
             const float* __restrict__ w_xyz,    const float* __restrict__ b_xyz,
             const float* __restrict__ w2)
{
    int t = threadIdx.x, lane = t & 31, w = t >> 5;
    int row = blockIdx.x * K1_WARPS + w;
    unsigned lmask = (1u << lane) - 1u;

    // fold w2 transpose into the first 64 blocks (1 entry/thread)
    if (blockIdx.x < 64) {
        int i = blockIdx.x * 256 + t;
        int k = i >> 8, o = i & 255;
        g_w2T[k][o] = w2[o*C1 + k];
    }

    __shared__ int s_idx[K1_WARPS][KNN];

    const float* __restrict__ drow = dist + (size_t)row * NPTS;
    float r = radius[row];           // issued concurrently with first chunks
    int cnt = 0;

    if (r >= 0.04f) {
        // fast path: 64-elem chunks, 4-deep prefetch (256 elems in flight)
        float da[4], db[4];
#pragma unroll
        for (int q = 0; q < 4; q++) {
            da[q] = drow[q*64 + lane];
            db[q] = drow[q*64 + 32 + lane];
        }
        int base = 0;
#pragma unroll 1
        while (true) {
            unsigned m0 = __ballot_sync(0xffffffffu, da[0] <= r);
            if (da[0] <= r) {
                int pos = cnt + __popc(m0 & lmask);
                if (pos < KNN) s_idx[w][pos] = base + lane;
            }
            cnt += __popc(m0);
            unsigned m1 = __ballot_sync(0xffffffffu, db[0] <= r);
            if (db[0] <= r) {
                int pos = cnt + __popc(m1 & lmask);
                if (pos < KNN) s_idx[w][pos] = base + 32 + lane;
            }
            cnt += __popc(m1);
            if (cnt >= KNN || base + 64 >= NPTS) break;
#pragma unroll
            for (int q = 0; q < 3; q++) { da[q] = da[q+1]; db[q] = db[q+1]; }
            int nf = base + 256;
            if (nf + 64 <= NPTS) { da[3] = drow[nf + lane]; db[3] = drow[nf + 32 + lane]; }
            else                 { da[3] = 2.0f;            db[3] = 2.0f; }
            base += 64;
        }
    } else {
        // slow path (rare): 256-elem chunks, 3-deep prefetch (MLP ~24)
        float buf[4][8];
#pragma unroll
        for (int q = 0; q < 4; q++)
#pragma unroll
            for (int s = 0; s < 8; s++) buf[q][s] = drow[q*256 + s*32 + lane];
        int base = 0;
#pragma unroll 1
        while (true) {
#pragma unroll
            for (int s = 0; s < 8; s++) {
                float d = buf[0][s];
                unsigned m = __ballot_sync(0xffffffffu, d <= r);
                if (d <= r) {
                    int pos = cnt + __popc(m & lmask);
                    if (pos < KNN) s_idx[w][pos] = base + s*32 + lane;
                }
                cnt += __popc(m);
            }
            if (cnt >= KNN || base + 256 >= NPTS) break;
            int nb = base + 1024;
#pragma unroll
            for (int q = 0; q < 3; q++)
#pragma unroll
                for (int s = 0; s < 8; s++) buf[q][s] = buf[q+1][s];
#pragma unroll
            for (int s = 0; s < 8; s++)
                buf[3][s] = (nb < NPTS) ? drow[nb + s*32 + lane] : 2.0f;
            base += 256;
        }
    }
    __syncwarp();

    // pad with first valid index (or N-1 clamp when none)
    if (lane < KNN) {
        int first = (cnt > 0) ? s_idx[w][0] : (NPTS - 1);
        int v = (lane < cnt) ? s_idx[w][lane] : first;
        s_idx[w][lane] = v;
    }
    __syncwarp();

    // BN0 stats + h min/max: lane = channel
    float a0=w_xyz[lane*9+0], a1=w_xyz[lane*9+1], a2=w_xyz[lane*9+2];
    float a3=w_xyz[lane*9+3], a4=w_xyz[lane*9+4], a5=w_xyz[lane*9+5];
    float a6=w_xyz[lane*9+6], a7=w_xyz[lane*9+7], a8=w_xyz[lane*9+8];
    float wc0=a0-a6, wc1=a1-a7, wc2=a2-a8;
    float wp0=a3+a6, wp1=a4+a7, wp2=a5+a8;
    float cx = centroid[row*3+0], cy = centroid[row*3+1], cz = centroid[row*3+2];
    const float* __restrict__ xb = xyz + (size_t)(row >> 11) * NPTS * 3;
    float hbase = b_xyz[lane] + wc0*cx + wc1*cy + wc2*cz;

    float ls = 0.0f, lss = 0.0f, hmin = 1e30f, hmax = -1e30f;
#pragma unroll
    for (int k = 0; k < KNN; k++) {
        int id = s_idx[w][k];           // warp-uniform -> broadcast
        float px = xb[id*3+0], py = xb[id*3+1], pz = xb[id*3+2];
        float h = hbase + wp0*px + wp1*py + wp2*pz;
        ls += h; lss += h*h;
        hmin = fminf(hmin, h); hmax = fmaxf(hmax, h);
    }
    g_hmm[row][0][lane] = hmin;
    g_hmm[row][1][lane] = hmax;
    int rep = row & (NB0 - 1);
    atomicAdd(&BINS0(rep, lane),      ls);
    atomicAdd(&BINS0(rep, C0 + lane), lss);
}

// ---------------- K2: BN0 hull + GELU + w1 -> h1, BN1 stats (no gather) ----------------
#define K2_RPW 4           // rows per warp
__global__ __launch_bounds__(256)
void k2(const float* __restrict__ g0, const float* __restrict__ be0,
        const float* __restrict__ w1)
{
    int t = threadIdx.x, lane = t & 31, w = t >> 5;
    __shared__ float s_sc0[C0], s_bi0[C0];
    __shared__ float s_w1[C1*33];
    __shared__ float s_sum[C1], s_ssq[C1];

    if (t < C0) {
        float s = 0.0f, ss = 0.0f;
        for (int rep = 0; rep < NB0; rep++) { s += BINS0(rep, t); ss += BINS0(rep, C0 + t); }
        float inv = 1.0f / (float)(NROWS * KNN);
        float mean = s * inv;
        float var  = ss * inv - mean * mean;
        float sc   = g0[t] * rsqrtf(var + EPSB);
        s_sc0[t] = sc; s_bi0[t] = be0[t] - mean * sc;
    }
    for (int i = t; i < C1*C0; i += 256) {
        int o = i >> 5, cc = i & 31;
        s_w1[o*33 + cc] = w1[i];
    }
    if (t < C1) { s_sum[t] = 0.0f; s_ssq[t] = 0.0f; }
    __syncthreads();

    float sc = s_sc0[lane], bi = s_bi0[lane];
    float sum0 = 0.0f, ssq0 = 0.0f, sum1 = 0.0f, ssq1 = 0.0f;

#pragma unroll
    for (int rr = 0; rr < K2_RPW; rr++) {
        int row = blockIdx.x * (8*K2_RPW) + w * K2_RPW + rr;
        float hmin = g_hmm[row][0][lane];
        float hmax = g_hmm[row][1][lane];
        float e0 = hmin * sc + bi;
        float e1 = hmax * sc + bi;
        float lo = fminf(e0, e1), hi = fmaxf(e0, e1);
        float m = fmaxf(gelu_exact(lo), gelu_exact(hi));

        float acc0 = 0.0f, acc1 = 0.0f;
#pragma unroll
        for (int cc = 0; cc < C0; cc++) {
            float xv = __shfl_sync(0xffffffffu, m, cc);
            acc0 += s_w1[lane*33 + cc] * xv;
            acc1 += s_w1[(lane+32)*33 + cc] * xv;
        }
        g_h1[(size_t)row*C1 + lane]      = acc0;
        g_h1[(size_t)row*C1 + lane + 32] = acc1;
        sum0 += acc0; ssq0 += acc0*acc0;
        sum1 += acc1; ssq1 += acc1*acc1;
    }

    atomicAdd(&s_sum[lane],      sum0);
    atomicAdd(&s_ssq[lane],      ssq0);
    atomicAdd(&s_sum[lane+32],   sum1);
    atomicAdd(&s_ssq[lane+32],   ssq1);
    __syncthreads();
    if (t < C1) {
        int rep = blockIdx.x & (NB - 1);
        atomicAdd(&BINS1(rep, t),      s_sum[t]);
        atomicAdd(&BINS1(rep, C1 + t), s_ssq[t]);
    }
}

// ---------------- K3: BN1+GELU fused + z = y @ w2^T, 8x4 tile, sw-pipelined ----------------
#define K3_R   32
#define K3_PAD (K3_R + 2)     // 34 floats/row: 8B-aligned row starts, low conflicts
__global__ __launch_bounds__(256)
void k3b(const float* __restrict__ g1, const float* __restrict__ be1)
{
    int t = threadIdx.x, lane = t & 31, w = t >> 5;
    int wc = w >> 2, wr = w & 3;            // warp-col (channels), warp-row (rows)
    int row0 = blockIdx.x * K3_R;
    int o0 = wc * 128 + lane * 4;           // 4 consecutive output channels
    int r0 = wr * 8;                        // 8 rows

    __shared__ float s_sc[C1], s_bi[C1];
    __shared__ float s_yT[C1][K3_PAD];
    __shared__ float s_sum[C2], s_ssq[C2];

    s_sum[t] = 0.0f; s_ssq[t] = 0.0f;
    if (t < C1) {
        float s = 0.0f, ss = 0.0f;
#pragma unroll
        for (int rep = 0; rep < NB; rep++) { s += BINS1(rep, t); ss += BINS1(rep, C1 + t); }
        float inv = 1.0f / (float)NROWS;
        float mean = s * inv;
        float var  = ss * inv - mean * mean;
        float sc   = g1[t] * rsqrtf(var + EPSB);
        s_sc[t] = sc; s_bi[t] = be1[t] - mean * sc;
    }
    __syncthreads();

    // load h1 tile coalesced, BN1+GELU, store transposed [k][r]
#pragma unroll
    for (int i = 0; i < (K3_R*C1)/256; i++) {   // 8
        int j = t + i*256;
        int r = j >> 6, c = j & 63;
        float v = g_h1[(size_t)(row0 + r)*C1 + c];
        s_yT[c][r] = gelu_exact(v * s_sc[c] + s_bi[c]);
    }
    __syncthreads();

    unsigned long long acc[4][4];               // [channel j][row-pair p]
#pragma unroll
    for (int j = 0; j < 4; j++)
#pragma unroll
        for (int p = 0; p < 4; p++) acc[j][p] = 0ull;

    const float4* __restrict__ wt4 = reinterpret_cast<const float4*>(&g_w2T[0][0]);
    const int widx = (o0 >> 2);

    // software pipeline: next-k operands fetched before current-k FFMA2s
    float4 wv = wt4[widx];
    unsigned long long y0, y1, y2, y3;
    {
        const unsigned long long* yp =
            reinterpret_cast<const unsigned long long*>(&s_yT[0][r0]);
        y0 = yp[0]; y1 = yp[1]; y2 = yp[2]; y3 = yp[3];
    }

#pragma unroll 16
    for (int k = 0; k < C1 - 1; k++) {
        // prefetch k+1
        float4 wn = wt4[(k+1)*(C2/4) + widx];
        const unsigned long long* yp =
            reinterpret_cast<const unsigned long long*>(&s_yT[k+1][r0]);
        unsigned long long n0 = yp[0], n1 = yp[1], n2 = yp[2], n3 = yp[3];

        unsigned long long w0, w1, w2, w3;
        asm("mov.b64 %0, {%1, %1};" : "=l"(w0) : "f"(wv.x));
        asm("mov.b64 %0, {%1, %1};" : "=l"(w1) : "f"(wv.y));
        asm("mov.b64 %0, {%1, %1};" : "=l"(w2) : "f"(wv.z));
        asm("mov.b64 %0, {%1, %1};" : "=l"(w3) : "f"(wv.w));
        asm("fma.rn.f32x2 %0, %1, %2, %0;" : "+l"(acc[0][0]) : "l"(y0), "l"(w0));
        asm("fma.rn.f32x2 %0, %1, %2, %0;" : "+l"(acc[0][1]) : "l"(y1), "l"(w0));
        asm("fma.rn.f32x2 %0, %1, %2, %0;" : "+l"(acc[0][2]) : "l"(y2), "l"(w0));
        asm("fma.rn.f32x2 %0, %1, %2, %0;" : "+l"(acc[0][3]) : "l"(y3), "l"(w0));
        asm("fma.rn.f32x2 %0, %1, %2, %0;" : "+l"(acc[1][0]) : "l"(y0), "l"(w1));
        asm("fma.rn.f32x2 %0, %1, %2, %0;" : "+l"(acc[1][1]) : "l"(y1), "l"(w1));
        asm("fma.rn.f32x2 %0, %1, %2, %0;" : "+l"(acc[1][2]) : "l"(y2), "l"(w1));
        asm("fma.rn.f32x2 %0, %1, %2, %0;" : "+l"(acc[1][3]) : "l"(y3), "l"(w1));
        asm("fma.rn.f32x2 %0, %1, %2, %0;" : "+l"(acc[2][0]) : "l"(y0), "l"(w2));
        asm("fma.rn.f32x2 %0, %1, %2, %0;" : "+l"(acc[2][1]) : "l"(y1), "l"(w2));
        asm("fma.rn.f32x2 %0, %1, %2, %0;" : "+l"(acc[2][2]) : "l"(y2), "l"(w2));
        asm("fma.rn.f32x2 %0, %1, %2, %0;" : "+l"(acc[2][3]) : "l"(y3), "l"(w2));
        asm("fma.rn.f32x2 %0, %1, %2, %0;" : "+l"(acc[3][0]) : "l"(y0), "l"(w3));
        asm("fma.rn.f32x2 %0, %1, %2, %0;" : "+l"(acc[3][1]) : "l"(y1), "l"(w3));
        asm("fma.rn.f32x2 %0, %1, %2, %0;" : "+l"(acc[3][2]) : "l"(y2), "l"(w3));
        asm("fma.rn.f32x2 %0, %1, %2, %0;" : "+l"(acc[3][3]) : "l"(y3), "l"(w3));

        wv = wn; y0 = n0; y1 = n1; y2 = n2; y3 = n3;
    }
    {   // peeled last iteration (k = C1-1)
        unsigned long long w0, w1, w2, w3;
        asm("mov.b64 %0, {%1, %1};" : "=l"(w0) : "f"(wv.x));
        asm("mov.b64 %0, {%1, %1};" : "=l"(w1) : "f"(wv.y));
        asm("mov.b64 %0, {%1, %1};" : "=l"(w2) : "f"(wv.z));
        asm("mov.b64 %0, {%1, %1};" : "=l"(w3) : "f"(wv.w));
        asm("fma.rn.f32x2 %0, %1, %2, %0;" : "+l"(acc[0][0]) : "l"(y0), "l"(w0));
        asm("fma.rn.f32x2 %0, %1, %2, %0;" : "+l"(acc[0][1]) : "l"(y1), "l"(w0));
        asm("fma.rn.f32x2 %0, %1, %2, %0;" : "+l"(acc[0][2]) : "l"(y2), "l"(w0));
        asm("fma.rn.f32x2 %0, %1, %2, %0;" : "+l"(acc[0][3]) : "l"(y3), "l"(w0));
        asm("fma.rn.f32x2 %0, %1, %2, %0;" : "+l"(acc[1][0]) : "l"(y0), "l"(w1));
        asm("fma.rn.f32x2 %0, %1, %2, %0;" : "+l"(acc[1][1]) : "l"(y1), "l"(w1));
        asm("fma.rn.f32x2 %0, %1, %2, %0;" : "+l"(acc[1][2]) : "l"(y2), "l"(w1));
        asm("fma.rn.f32x2 %0, %1, %2, %0;" : "+l"(acc[1][3]) : "l"(y3), "l"(w1));
        asm("fma.rn.f32x2 %0, %1, %2, %0;" : "+l"(acc[2][0]) : "l"(y0), "l"(w2));
        asm("fma.rn.f32x2 %0, %1, %2, %0;" : "+l"(acc[2][1]) : "l"(y1), "l"(w2));
        asm("fma.rn.f32x2 %0, %1, %2, %0;" : "+l"(acc[2][2]) : "l"(y2), "l"(w2));
        asm("fma.rn.f32x2 %0, %1, %2, %0;" : "+l"(acc[2][3]) : "l"(y3), "l"(w2));
        asm("fma.rn.f32x2 %0, %1, %2, %0;" : "+l"(acc[3][0]) : "l"(y0), "l"(w3));
        asm("fma.rn.f32x2 %0, %1, %2, %0;" : "+l"(acc[3][1]) : "l"(y1), "l"(w3));
        asm("fma.rn.f32x2 %0, %1, %2, %0;" : "+l"(acc[3][2]) : "l"(y2), "l"(w3));
        asm("fma.rn.f32x2 %0, %1, %2, %0;" : "+l"(acc[3][3]) : "l"(y3), "l"(w3));
    }

    // epilogue: store z (coalesced float4 per row) + per-channel partial stats
    float csum[4] = {0,0,0,0}, cssq[4] = {0,0,0,0};
#pragma unroll
    for (int p = 0; p < 4; p++) {
        float4 lo, hi;
        float zl[4], zh[4];
#pragma unroll
        for (int j = 0; j < 4; j++) {
            zl[j] = __uint_as_float((unsigned)(acc[j][p] & 0xffffffffull));
            zh[j] = __uint_as_float((unsigned)(acc[j][p] >> 32));
            csum[j] += zl[j] + zh[j];
            cssq[j] += zl[j]*zl[j] + zh[j]*zh[j];
        }
        lo.x=zl[0]; lo.y=zl[1]; lo.z=zl[2]; lo.w=zl[3];
        hi.x=zh[0]; hi.y=zh[1]; hi.z=zh[2]; hi.w=zh[3];
        int ra = row0 + r0 + 2*p;
        *reinterpret_cast<float4*>(&g_z[(size_t)ra*C2 + o0])     = lo;
        *reinterpret_cast<float4*>(&g_z[(size_t)(ra+1)*C2 + o0]) = hi;
    }
#pragma unroll
    for (int j = 0; j < 4; j++) {
        atomicAdd(&s_sum[o0 + j], csum[j]);
        atomicAdd(&s_ssq[o0 + j], cssq[j]);
    }
    __syncthreads();
    int rep = blockIdx.x & (NB - 1);
    atomicAdd(&BINS2(rep, t),      s_sum[t]);
    atomicAdd(&BINS2(rep, C2 + t), s_ssq[t]);
}

// ---------------- K4: BN2 normalize -> out (front-batched MLP=4) ----------------
#define K4_GRID 512
__global__ __launch_bounds__(256)
void k4(const float* __restrict__ g2, const float* __restrict__ be2,
        float* __restrict__ out)
{
    int t = threadIdx.x;
    __shared__ float s_sc[C2], s_bi[C2];
    {
        float s = 0.0f, ss = 0.0f;
#pragma unroll
        for (int rep = 0; rep < NB; rep++) { s += BINS2(rep, t); ss += BINS2(rep, C2 + t); }
        float inv = 1.0f / (float)NROWS;
        float mean = s * inv;
        float var  = ss * inv - mean * mean;
        float sc   = g2[t] * rsqrtf(var + EPSB);
        s_sc[t] = sc; s_bi[t] = be2[t] - mean * sc;
    }
    __syncthreads();
    const float4* __restrict__ z4 = reinterpret_cast<const float4*>(g_z);
    float4* __restrict__ o4 = reinterpret_cast<float4*>(out);
    const int S = K4_GRID * 256;                 // 131072
    // total4 = 524288 = 4*S exactly; i mod 64 invariant across batches
    int i0 = blockIdx.x * 256 + t;
    float4 v0 = z4[i0], v1 = z4[i0 + S], v2 = z4[i0 + 2*S], v3 = z4[i0 + 3*S];
    int c = (i0 & 63) * 4;
    float sc0 = s_sc[c+0], sc1 = s_sc[c+1], sc2 = s_sc[c+2], sc3 = s_sc[c+3];
    float bi0 = s_bi[c+0], bi1 = s_bi[c+1], bi2 = s_bi[c+2], bi3 = s_bi[c+3];
    v0.x = v0.x*sc0 + bi0; v0.y = v0.y*sc1 + bi1; v0.z = v0.z*sc2 + bi2; v0.w = v0.w*sc3 + bi3;
    v1.x = v1.x*sc0 + bi0; v1.y = v1.y*sc1 + bi1; v1.z = v1.z*sc2 + bi2; v1.w = v1.w*sc3 + bi3;
    v2.x = v2.x*sc0 + bi0; v2.y = v2.y*sc1 + bi1; v2.z = v2.z*sc2 + bi2; v2.w = v2.w*sc3 + bi3;
    v3.x = v3.x*sc0 + bi0; v3.y = v3.y*sc1 + bi1; v3.z = v3.z*sc2 + bi2; v3.w = v3.w*sc3 + bi3;
    o4[i0]       = v0;
    o4[i0 +   S] = v1;
    o4[i0 + 2*S] = v2;
    o4[i0 + 3*S] = v3;
}

// ---------------- launch ----------------
extern "C" void kernel_launch(void* const* d_in, const int* in_sizes, int n_in,
                              void* d_out, int out_size)
{
    const float* centroid = (const float*)d_in[0];
    const float* xyz      = (const float*)d_in[1];
    const float* radius   = (const float*)d_in[2];
    const float* dist     = (const float*)d_in[3];
    const float* w_xyz    = (const float*)d_in[4];
    const float* b_xyz    = (const float*)d_in[5];
    const float* g0       = (const float*)d_in[6];
    const float* be0      = (const float*)d_in[7];
    const float* w1       = (const float*)d_in[8];
    const float* g1       = (const float*)d_in[9];
    const float* be1      = (const float*)d_in[10];
    const float* w2       = (const float*)d_in[11];
    const float* g2       = (const float*)d_in[12];
    const float* be2      = (const float*)d_in[13];
    float* out = (float*)d_out;

    // clear all stat bins with a single captured memset (no alloc)
    void* bins_ptr = nullptr;
    cudaGetSymbolAddress(&bins_ptr, g_bins);
    cudaMemsetAsync(bins_ptr, 0, BINS_TOTAL * sizeof(float));

    k1_scan<<<NROWS / K1_WARPS, 256>>>(centroid, xyz, radius, dist, w_xyz, b_xyz, w2);
    k2<<<NROWS / (8*K2_RPW), 256>>>(g0, be0, w1);
    k3b<<<NROWS / K3_R, 256>>>(g1, be1);
    k4<<<K4_GRID, 256>>>(g2, be2, out);
}